// round 7
// baseline (speedup 1.0000x reference)
#include <cuda_runtime.h>
#include <cooperative_groups.h>
#include <math.h>
#include <stdint.h>

namespace cg = cooperative_groups;

// ---------------------------------------------------------------------------
// LogNCDE depth-2 log-ODE scan, 4-CTA cluster per batch element.
// Rank r owns channels {2r,2r+1} and Wv2 rows [128r,128r+128).
// v6 engine (register weight tiles, smem float4 partials, cluster.sync
// exchanges, hoisted readout, precomputed C, fast activations) with all
// dot products converted to packed fp32 FMAs (PTX fma.rn.f32x2 -> FFMA2).
// ---------------------------------------------------------------------------

namespace {
constexpr int kB   = 32;
constexpr int kT   = 2049;
constexpr int kD   = 8;
constexpr int kS   = 64;
constexpr int kH   = 128;
constexpr int kP   = 28;
constexpr int kNW  = 128;
constexpr int kWin = 16;
constexpr int kOut = 8;
constexpr int CL   = 4;
constexpr int NT   = 256;

// shared-memory layout (float offsets; float4-aligned)
constexpr int OFF_SIGS  = 0;        // [n<128][36]
constexpr int OFF_CH    = 4608;     // [n<128][16] per-rank C coeffs
constexpr int OFF_BV0   = 6656;     // 128
constexpr int OFF_BV1   = 6784;     // 128
constexpr int OFF_BV2S  = 6912;     // 128
constexpr int OFF_WR    = 7040;     // [o<8][a<64]
constexpr int OFF_BR    = 7552;     // 8 (+pad)
constexpr int OFF_HH    = 7568;     // [n<129][64] h history
constexpr int OFF_Z0    = 15824;    // 128
constexpr int OFF_D0    = 15952;    // 128
constexpr int OFF_Z1    = 16080;    // 128
constexpr int OFF_D1    = 16208;    // 128
constexpr int OFF_V     = 16336;    // 2 x 512 double buffer
constexpr int OFF_TDS   = 17360;    // 128
constexpr int OFF_WT    = 17488;    // 2 x 64
constexpr int OFF_PT    = 17616;    // 2 x 128
constexpr int OFF_UT    = 17872;    // 2 x 128
constexpr int OFF_RSLOT = 18128;    // 4 x 64
constexpr int OFF_PART  = 18384;    // 2 x 8 x 128 partials
constexpr int SMEMF     = 20432;    // ~82 KB
}  // namespace

static __device__ const int c_II[kP] =
    {0,0,0,0,0,0,0,1,1,1,1,1,1,2,2,2,2,2,3,3,3,3,4,4,4,5,5,6};
static __device__ const int c_JJ[kP] =
    {1,2,3,4,5,6,7,2,3,4,5,6,7,3,4,5,6,7,4,5,6,7,5,6,7,6,7,7};

using u64t = unsigned long long;

__device__ __forceinline__ int pidx(int i, int j) {   // Lyndon pair index, i<j
    return 7 * i - (i * (i - 1)) / 2 + (j - i - 1);
}
// packed fp32x2 fma: r.lo = a.lo*b.lo + c.lo ; r.hi = a.hi*b.hi + c.hi
__device__ __forceinline__ u64t ffma2(u64t a, u64t b, u64t c) {
    u64t r;
    asm("fma.rn.f32x2 %0, %1, %2, %3;" : "=l"(r) : "l"(a), "l"(b), "l"(c));
    return r;
}
__device__ __forceinline__ float fold2(u64t a) {
    float lo, hi;
    asm("mov.b64 {%0, %1}, %2;" : "=f"(lo), "=f"(hi) : "l"(a));
    return lo + hi;
}
__device__ __forceinline__ float tanh_ap(float x) {
    float r; asm("tanh.approx.f32 %0, %1;" : "=f"(r) : "f"(x)); return r;
}
// fast softplus value + sigmoid derivative from one exp
__device__ __forceinline__ void sp_sg(float s, float& z, float& d) {
    if (s > 20.f) { z = s; d = 1.f; }
    else {
        float e = __expf(s);
        float inv = __frcp_rn(1.f + e);
        z = __logf(1.f + e);
        d = e * inv;
    }
}
__device__ __forceinline__ float sp_f(float x) {   // accurate (one-time h0)
    return (x > 20.f) ? x : log1pf(expf(x));
}

__global__ __launch_bounds__(NT, 1) __cluster_dims__(CL, 1, 1)
void logncde_v7_kernel(
    const float* __restrict__ x,
    const float* __restrict__ Wi0, const float* __restrict__ bi0,
    const float* __restrict__ Wi1, const float* __restrict__ bi1,
    const float* __restrict__ Wi2, const float* __restrict__ bi2,
    const float* __restrict__ Wv0, const float* __restrict__ bv0,
    const float* __restrict__ Wv1, const float* __restrict__ bv1,
    const float* __restrict__ Wv2, const float* __restrict__ bv2,
    const float* __restrict__ Wr,  const float* __restrict__ br,
    float* __restrict__ out)
{
    extern __shared__ float sm[];
    cg::cluster_group cluster = cg::this_cluster();
    const int t    = threadIdx.x;
    const int rank = (int)cluster.block_rank();
    const int b    = blockIdx.x >> 2;
    const int d0g  = 2 * rank;
    const int og   = t & 31;     // output group: rows 4og..4og+3
    const int kg   = t >> 5;     // k-octant == warp id (broadcast-friendly)

    float* peer[CL - 1];
    #pragma unroll
    for (int p = 1; p < CL; p++)
        peer[p - 1] = cluster.map_shared_rank(sm, (rank + p) & (CL - 1));

    // ---- register weight tiles as packed f32x2 pairs ----
    // Wv0: 4 rows x 2 float4-chunks -> 16 u64 ; Wv1/Wv2: 4 rows x 4 -> 32 u64.
    // wXp[row*(2*J) + j*2 + half]
    u64t w0p[16], w1p[32], w2p[32];
    {
        const ulonglong2* W0 = (const ulonglong2*)Wv0;   // [128][16] 16B units
        #pragma unroll
        for (int r = 0; r < 4; r++)
            #pragma unroll
            for (int j = 0; j < 2; j++) {
                ulonglong2 v = W0[(4 * og + r) * 16 + kg * 2 + j];
                w0p[r * 4 + j * 2]     = v.x;
                w0p[r * 4 + j * 2 + 1] = v.y;
            }
        const ulonglong2* W1 = (const ulonglong2*)Wv1;   // [128][32]
        #pragma unroll
        for (int r = 0; r < 4; r++)
            #pragma unroll
            for (int j = 0; j < 4; j++) {
                ulonglong2 v = W1[(4 * og + r) * 32 + kg * 4 + j];
                w1p[r * 8 + j * 2]     = v.x;
                w1p[r * 8 + j * 2 + 1] = v.y;
            }
        const ulonglong2* W2 = (const ulonglong2*)Wv2;   // [512][32]
        #pragma unroll
        for (int r = 0; r < 4; r++)
            #pragma unroll
            for (int j = 0; j < 4; j++) {
                ulonglong2 v = W2[(kH * rank + 4 * og + r) * 32 + kg * 4 + j];
                w2p[r * 8 + j * 2]     = v.x;
                w2p[r * 8 + j * 2 + 1] = v.y;
            }
    }

    // ---- one-time smem staging: biases, readout, signatures ----
    for (int i = t; i < kH; i += NT) {
        sm[OFF_BV0 + i]  = bv0[i];
        sm[OFF_BV1 + i]  = bv1[i];
        sm[OFF_BV2S + i] = bv2[kH * rank + i];
    }
    for (int i = t; i < kOut * kS; i += NT) sm[OFF_WR + i] = Wr[i];
    if (t < kOut) sm[OFF_BR + t] = br[t];

    if (t < kNW) {
        const float* xb = x + (size_t)b * kT * kD + (size_t)t * kWin * kD;
        float cum[kD], prev[kD], Mm[kD * kD];
        #pragma unroll
        for (int i = 0; i < kD; i++) { cum[i] = 0.f; prev[i] = xb[i]; }
        #pragma unroll
        for (int i = 0; i < kD * kD; i++) Mm[i] = 0.f;
        for (int w = 0; w < kWin; w++) {
            float dl[kD];
            #pragma unroll
            for (int j = 0; j < kD; j++) {
                float c = xb[(w + 1) * kD + j];
                dl[j] = c - prev[j];
                prev[j] = c;
            }
            #pragma unroll
            for (int i = 0; i < kD; i++)
                #pragma unroll
                for (int j = 0; j < kD; j++)
                    Mm[i * kD + j] = fmaf(cum[i], dl[j], Mm[i * kD + j]);
            #pragma unroll
            for (int i = 0; i < kD; i++) cum[i] += dl[i];
        }
        float* sgw = &sm[OFF_SIGS + t * 36];
        #pragma unroll
        for (int i = 0; i < kD; i++) sgw[i] = cum[i];
        #pragma unroll
        for (int p = 0; p < kP; p++) {
            int i = c_II[p], j = c_JJ[p];
            sgw[8 + p] = 0.5f * (Mm[i * kD + j] - Mm[j * kD + i]);
        }
    }
    __syncthreads();

    // ---- one-time: precompute C coefficients for all steps ----
    for (int i = t; i < kNW * 16; i += NT) {
        int n = i >> 4, j = i & 15;
        int dl = j >> 3, e = j & 7;
        int d = d0g + dl;
        const float* sgn = &sm[OFF_SIGS + n * 36];
        float v = 0.f;
        if (e < d)      v =  sgn[8 + pidx(e, d)];
        else if (e > d) v = -sgn[8 + pidx(d, e)];
        sm[OFF_CH + n * 16 + dl * 8 + e] = v;
    }

    // ---- one-time: initial MLP h0 (accurate path; replicated) ----
    {
        const float* x0 = x + (size_t)b * kT * kD;
        if (t < kH) {
            float acc = bi0[t];
            #pragma unroll
            for (int k = 0; k < kD; k++) acc = fmaf(Wi0[t * kD + k], x0[k], acc);
            sm[OFF_Z0 + t] = sp_f(acc);
        }
        __syncthreads();
        if (t < kH) {
            float acc = bi1[t];
            #pragma unroll 16
            for (int k = 0; k < kH; k++) acc = fmaf(Wi1[t * kH + k], sm[OFF_Z0 + k], acc);
            sm[OFF_Z1 + t] = sp_f(acc);
        }
        __syncthreads();
        if (t < kS) {
            float acc = bi2[t];
            #pragma unroll 16
            for (int k = 0; k < kH; k++) acc = fmaf(Wi2[t * kH + k], sm[OFF_Z1 + k], acc);
            sm[OFF_HH + t] = acc;
        }
        __syncthreads();
    }

    cluster.sync();

    float4* part4 = (float4*)&sm[OFF_PART];

    // ============================ scan loop ============================
    for (int n = 0; n < kNW; n++) {
        const float* hcur = &sm[OFF_HH + n * kS];
        const int parV = (n & 1) * 512;

        // --- A: partials of z0 = Wv0 h  (packed fma)
        {
            const ulonglong2* h2 = (const ulonglong2*)hcur;
            u64t a0 = 0, a1 = 0, a2 = 0, a3 = 0;
            #pragma unroll
            for (int j = 0; j < 2; j++) {
                ulonglong2 hv = h2[kg * 2 + j];
                a0 = ffma2(w0p[0 * 4 + j * 2], hv.x, a0);
                a0 = ffma2(w0p[0 * 4 + j * 2 + 1], hv.y, a0);
                a1 = ffma2(w0p[1 * 4 + j * 2], hv.x, a1);
                a1 = ffma2(w0p[1 * 4 + j * 2 + 1], hv.y, a1);
                a2 = ffma2(w0p[2 * 4 + j * 2], hv.x, a2);
                a2 = ffma2(w0p[2 * 4 + j * 2 + 1], hv.y, a2);
                a3 = ffma2(w0p[3 * 4 + j * 2], hv.x, a3);
                a3 = ffma2(w0p[3 * 4 + j * 2 + 1], hv.y, a3);
            }
            part4[kg * 32 + og] = make_float4(fold2(a0), fold2(a1), fold2(a2), fold2(a3));
        }
        __syncthreads();
        if (t < kH) {
            float s = sm[OFF_BV0 + t];
            #pragma unroll
            for (int q = 0; q < 8; q++) s += sm[OFF_PART + q * kH + t];
            float z, d;
            sp_sg(s, z, d);
            sm[OFF_Z0 + t] = z; sm[OFF_D0 + t] = d;
        }
        __syncthreads();

        // --- B: partials of z1 = Wv1 z0
        {
            const ulonglong2* z2 = (const ulonglong2*)&sm[OFF_Z0];
            u64t a0 = 0, a1 = 0, a2 = 0, a3 = 0;
            #pragma unroll
            for (int j = 0; j < 4; j++) {
                ulonglong2 zv = z2[kg * 4 + j];
                a0 = ffma2(w1p[0 * 8 + j * 2], zv.x, a0);
                a0 = ffma2(w1p[0 * 8 + j * 2 + 1], zv.y, a0);
                a1 = ffma2(w1p[1 * 8 + j * 2], zv.x, a1);
                a1 = ffma2(w1p[1 * 8 + j * 2 + 1], zv.y, a1);
                a2 = ffma2(w1p[2 * 8 + j * 2], zv.x, a2);
                a2 = ffma2(w1p[2 * 8 + j * 2 + 1], zv.y, a2);
                a3 = ffma2(w1p[3 * 8 + j * 2], zv.x, a3);
                a3 = ffma2(w1p[3 * 8 + j * 2 + 1], zv.y, a3);
            }
            part4[kg * 32 + og] = make_float4(fold2(a0), fold2(a1), fold2(a2), fold2(a3));
        }
        __syncthreads();
        if (t < kH) {
            float s = sm[OFF_BV1 + t];
            #pragma unroll
            for (int q = 0; q < 8; q++) s += sm[OFF_PART + q * kH + t];
            float z, d;
            sp_sg(s, z, d);
            sm[OFF_Z1 + t] = z; sm[OFF_D1 + t] = d;
        }
        __syncthreads();

        // --- C: partials of V slice = Wv2_slice z1
        {
            const ulonglong2* z2 = (const ulonglong2*)&sm[OFF_Z1];
            u64t a0 = 0, a1 = 0, a2 = 0, a3 = 0;
            #pragma unroll
            for (int j = 0; j < 4; j++) {
                ulonglong2 zv = z2[kg * 4 + j];
                a0 = ffma2(w2p[0 * 8 + j * 2], zv.x, a0);
                a0 = ffma2(w2p[0 * 8 + j * 2 + 1], zv.y, a0);
                a1 = ffma2(w2p[1 * 8 + j * 2], zv.x, a1);
                a1 = ffma2(w2p[1 * 8 + j * 2 + 1], zv.y, a1);
                a2 = ffma2(w2p[2 * 8 + j * 2], zv.x, a2);
                a2 = ffma2(w2p[2 * 8 + j * 2 + 1], zv.y, a2);
                a3 = ffma2(w2p[3 * 8 + j * 2], zv.x, a3);
                a3 = ffma2(w2p[3 * 8 + j * 2 + 1], zv.y, a3);
            }
            part4[kg * 32 + og] = make_float4(fold2(a0), fold2(a1), fold2(a2), fold2(a3));
        }
        __syncthreads();
        if (t < kH) {
            float s = sm[OFF_BV2S + t];
            #pragma unroll
            for (int q = 0; q < 8; q++) s += sm[OFF_PART + q * kH + t];
            float v = tanh_ap(s);
            int vi = OFF_V + parV + kH * rank + t;
            sm[vi] = v;
            sm[OFF_TDS + t] = 1.f - v * v;
            peer[0][vi] = v;
            peer[1][vi] = v;
            peer[2][vi] = v;
        }
        cluster.sync();   // V(n) gathered everywhere

        // --- D: tangents w_dl = sum_e C[dl,e] V_e (own 2 channels)
        if (t < kH) {
            int dl = t >> 6, a_ = t & 63;
            const float* cj = &sm[OFF_CH + n * 16 + dl * 8];
            float acc = 0.f;
            #pragma unroll
            for (int e = 0; e < kD; e++)
                acc = fmaf(cj[e], sm[OFF_V + parV + e * kS + a_], acc);
            sm[OFF_WT + dl * kS + a_] = acc;
        }
        __syncthreads();

        // --- E: partials of q_c = Wv0 wt_c (2 channels)
        {
            const ulonglong2* wt2 = (const ulonglong2*)&sm[OFF_WT];
            u64t a0 = 0, a1 = 0, a2 = 0, a3 = 0;    // channel 0, rows 0..3
            u64t b0 = 0, b1 = 0, b2 = 0, b3 = 0;    // channel 1
            #pragma unroll
            for (int j = 0; j < 2; j++) {
                ulonglong2 v0 = wt2[kg * 2 + j];
                ulonglong2 v1 = wt2[16 + kg * 2 + j];
                a0 = ffma2(w0p[0 * 4 + j * 2], v0.x, a0);
                a0 = ffma2(w0p[0 * 4 + j * 2 + 1], v0.y, a0);
                a1 = ffma2(w0p[1 * 4 + j * 2], v0.x, a1);
                a1 = ffma2(w0p[1 * 4 + j * 2 + 1], v0.y, a1);
                a2 = ffma2(w0p[2 * 4 + j * 2], v0.x, a2);
                a2 = ffma2(w0p[2 * 4 + j * 2 + 1], v0.y, a2);
                a3 = ffma2(w0p[3 * 4 + j * 2], v0.x, a3);
                a3 = ffma2(w0p[3 * 4 + j * 2 + 1], v0.y, a3);
                b0 = ffma2(w0p[0 * 4 + j * 2], v1.x, b0);
                b0 = ffma2(w0p[0 * 4 + j * 2 + 1], v1.y, b0);
                b1 = ffma2(w0p[1 * 4 + j * 2], v1.x, b1);
                b1 = ffma2(w0p[1 * 4 + j * 2 + 1], v1.y, b1);
                b2 = ffma2(w0p[2 * 4 + j * 2], v1.x, b2);
                b2 = ffma2(w0p[2 * 4 + j * 2 + 1], v1.y, b2);
                b3 = ffma2(w0p[3 * 4 + j * 2], v1.x, b3);
                b3 = ffma2(w0p[3 * 4 + j * 2 + 1], v1.y, b3);
            }
            part4[kg * 32 + og]       = make_float4(fold2(a0), fold2(a1), fold2(a2), fold2(a3));
            part4[256 + kg * 32 + og] = make_float4(fold2(b0), fold2(b1), fold2(b2), fold2(b3));
        }
        __syncthreads();
        {   // pt_c = D0 .* q_c  (all 256 threads)
            int dl = t >> 7, o = t & 127;
            float s = 0.f;
            #pragma unroll
            for (int q = 0; q < 8; q++)
                s += sm[OFF_PART + dl * 1024 + q * kH + o];
            sm[OFF_PT + dl * kH + o] = s * sm[OFF_D0 + o];
        }
        __syncthreads();

        // --- F: partials of u'_c = Wv1 pt_c (2 channels)
        {
            const ulonglong2* pt2 = (const ulonglong2*)&sm[OFF_PT];
            u64t a0 = 0, a1 = 0, a2 = 0, a3 = 0;
            u64t b0 = 0, b1 = 0, b2 = 0, b3 = 0;
            #pragma unroll
            for (int j = 0; j < 4; j++) {
                ulonglong2 v0 = pt2[kg * 4 + j];
                ulonglong2 v1 = pt2[32 + kg * 4 + j];
                a0 = ffma2(w1p[0 * 8 + j * 2], v0.x, a0);
                a0 = ffma2(w1p[0 * 8 + j * 2 + 1], v0.y, a0);
                a1 = ffma2(w1p[1 * 8 + j * 2], v0.x, a1);
                a1 = ffma2(w1p[1 * 8 + j * 2 + 1], v0.y, a1);
                a2 = ffma2(w1p[2 * 8 + j * 2], v0.x, a2);
                a2 = ffma2(w1p[2 * 8 + j * 2 + 1], v0.y, a2);
                a3 = ffma2(w1p[3 * 8 + j * 2], v0.x, a3);
                a3 = ffma2(w1p[3 * 8 + j * 2 + 1], v0.y, a3);
                b0 = ffma2(w1p[0 * 8 + j * 2], v1.x, b0);
                b0 = ffma2(w1p[0 * 8 + j * 2 + 1], v1.y, b0);
                b1 = ffma2(w1p[1 * 8 + j * 2], v1.x, b1);
                b1 = ffma2(w1p[1 * 8 + j * 2 + 1], v1.y, b1);
                b2 = ffma2(w1p[2 * 8 + j * 2], v1.x, b2);
                b2 = ffma2(w1p[2 * 8 + j * 2 + 1], v1.y, b2);
                b3 = ffma2(w1p[3 * 8 + j * 2], v1.x, b3);
                b3 = ffma2(w1p[3 * 8 + j * 2 + 1], v1.y, b3);
            }
            part4[kg * 32 + og]       = make_float4(fold2(a0), fold2(a1), fold2(a2), fold2(a3));
            part4[256 + kg * 32 + og] = make_float4(fold2(b0), fold2(b1), fold2(b2), fold2(b3));
        }
        __syncthreads();
        {   // ut_c = D1 .* u'_c
            int dl = t >> 7, o = t & 127;
            float s = 0.f;
            #pragma unroll
            for (int q = 0; q < 8; q++)
                s += sm[OFF_PART + dl * 1024 + q * kH + o];
            sm[OFF_UT + dl * kH + o] = s * sm[OFF_D1 + o];
        }
        __syncthreads();

        // --- G: partials of r = Wv2_slice u_{dl(row)}  (row-dependent RHS)
        {
            int dl = og >> 4;   // rows 4og..4og+3 all in channel dl
            const ulonglong2* u2 = (const ulonglong2*)&sm[OFF_UT + dl * kH];
            u64t a0 = 0, a1 = 0, a2 = 0, a3 = 0;
            #pragma unroll
            for (int j = 0; j < 4; j++) {
                ulonglong2 uv = u2[kg * 4 + j];
                a0 = ffma2(w2p[0 * 8 + j * 2], uv.x, a0);
                a0 = ffma2(w2p[0 * 8 + j * 2 + 1], uv.y, a0);
                a1 = ffma2(w2p[1 * 8 + j * 2], uv.x, a1);
                a1 = ffma2(w2p[1 * 8 + j * 2 + 1], uv.y, a1);
                a2 = ffma2(w2p[2 * 8 + j * 2], uv.x, a2);
                a2 = ffma2(w2p[2 * 8 + j * 2 + 1], uv.y, a2);
                a3 = ffma2(w2p[3 * 8 + j * 2], uv.x, a3);
                a3 = ffma2(w2p[3 * 8 + j * 2 + 1], uv.y, a3);
            }
            part4[kg * 32 + og] = make_float4(fold2(a0), fold2(a1), fold2(a2), fold2(a3));
        }
        __syncthreads();
        // G-reduce: apply TD, fold the 2 channels, push to peers
        if (t < kS) {
            float s0 = 0.f, s1 = 0.f;
            #pragma unroll
            for (int q = 0; q < 8; q++) {
                s0 += sm[OFF_PART + q * kH + t];
                s1 += sm[OFF_PART + q * kH + kS + t];
            }
            float rs = s0 * sm[OFF_TDS + t] + s1 * sm[OFF_TDS + kS + t];
            int ri = OFF_RSLOT + kS * rank + t;
            sm[ri] = rs;
            peer[0][ri] = rs;
            peer[1][ri] = rs;
            peer[2][ri] = rs;
        }
        cluster.sync();   // bracket partials gathered everywhere

        // --- H: h_{n+1} = h_n + a.V + sum_r rslot (replicated)
        if (t < kS) {
            const float* sgn = &sm[OFF_SIGS + n * 36];
            float acc = hcur[t];
            #pragma unroll
            for (int d = 0; d < kD; d++)
                acc = fmaf(sgn[d], sm[OFF_V + parV + d * kS + t], acc);
            #pragma unroll
            for (int p = 0; p < CL; p++)
                acc += sm[OFF_RSLOT + p * kS + t];
            sm[OFF_HH + (n + 1) * kS + t] = acc;
        }
        __syncthreads();
    }

    // ---- readout of the full h history (rank 0, parallel GEMM) ----
    if (rank == 0) {
        for (int idx = t; idx < (kNW + 1) * kOut; idx += NT) {
            int n = idx >> 3, o = idx & 7;
            float acc = sm[OFF_BR + o];
            const float* hh = &sm[OFF_HH + n * kS];
            #pragma unroll 16
            for (int a = 0; a < kS; a++)
                acc = fmaf(sm[OFF_WR + o * kS + a], hh[a], acc);
            out[((size_t)b * (kNW + 1) + n) * kOut + o] = acc;
        }
    }
    cluster.sync();   // no CTA exits while peers may still touch its smem
}

extern "C" void kernel_launch(void* const* d_in, const int* in_sizes, int n_in,
                              void* d_out, int out_size) {
    // metadata order: ts, x, Wi0,bi0, Wi1,bi1, Wi2,bi2, Wv0,bv0, Wv1,bv1, Wv2,bv2, Wr,br
    const float* x   = (const float*)d_in[1];
    const float* Wi0 = (const float*)d_in[2];
    const float* bi0 = (const float*)d_in[3];
    const float* Wi1 = (const float*)d_in[4];
    const float* bi1 = (const float*)d_in[5];
    const float* Wi2 = (const float*)d_in[6];
    const float* bi2 = (const float*)d_in[7];
    const float* Wv0 = (const float*)d_in[8];
    const float* bv0 = (const float*)d_in[9];
    const float* Wv1 = (const float*)d_in[10];
    const float* bv1 = (const float*)d_in[11];
    const float* Wv2 = (const float*)d_in[12];
    const float* bv2 = (const float*)d_in[13];
    const float* Wr  = (const float*)d_in[14];
    const float* br  = (const float*)d_in[15];
    float* out = (float*)d_out;

    cudaFuncSetAttribute(logncde_v7_kernel,
                         cudaFuncAttributeMaxDynamicSharedMemorySize,
                         SMEMF * (int)sizeof(float));
    logncde_v7_kernel<<<kB * CL, NT, SMEMF * sizeof(float)>>>(
        x, Wi0, bi0, Wi1, bi1, Wi2, bi2,
        Wv0, bv0, Wv1, bv1, Wv2, bv2, Wr, br, out);
}